// round 2
// baseline (speedup 1.0000x reference)
#include <cuda_runtime.h>

// VoxelMorph SpatialTransformer, trilinear, zero padding.
// src:  [B=2, C=2, 160, 192, 160] f32
// flow: [B=2, 3,   160, 192, 160] f32  (dz, dy, dx planes)
// out:  [B=2, C=2, 160, 192, 160] f32

namespace {
constexpr int D = 160, H = 192, W = 160, C = 2, B = 2;
constexpr long long N = (long long)D * H * W;

// output tile per block
constexpr int TZ = 8, TY = 16, TX = 32;
constexpr int R  = 3;                       // halo radius
constexpr int SZ = TZ + 1 + 2 * R;          // 15
constexpr int SY = TY + 1 + 2 * R;          // 23
constexpr int SX = TX + 1 + 2 * R;          // 39
constexpr int SXP = 40;                     // padded x stride
constexpr int CH  = SZ * SY * SXP;          // floats per channel tile = 13800
constexpr int SMEM_BYTES = 2 * CH * 4;      // 110400
constexpr int NZT = D / TZ;                 // 20 z-tiles
}

__global__ __launch_bounds__(512, 2)
void st_smem_kernel(const float* __restrict__ src,
                    const float* __restrict__ flow,
                    float* __restrict__ out)
{
    extern __shared__ float sm[];           // [2][SZ][SY][SXP]

    const int b   = blockIdx.z / NZT;
    const int z_t = (blockIdx.z % NZT) * TZ;
    const int y_t = blockIdx.y * TY;
    const int x_t = blockIdx.x * TX;

    const int tid  = threadIdx.y * 32 + threadIdx.x;
    const int lane = tid & 31;
    const int warp = tid >> 5;
    const int nwarps = (TY * TX) / 32;      // 16

    // ---- cooperative fill: rows of SX floats, coalesced ----
    const long long src_b = (long long)b * C * N;
    const int rows_total = 2 * SZ * SY;     // 690
    for (int r = warp; r < rows_total; r += nwarps) {
        const int ch  = r / (SZ * SY);
        const int rem = r - ch * (SZ * SY);
        const int sz  = rem / SY;
        const int sy  = rem - sz * SY;
        const int gz  = z_t - R + sz;
        const int gy  = y_t - R + sy;
        const bool rowvalid = ((unsigned)gz < (unsigned)D) && ((unsigned)gy < (unsigned)H);
        const float* srow = src + src_b + (long long)ch * N
                            + ((long long)gz * H + gy) * W + (x_t - R);
        float* drow = sm + ch * CH + (sz * SY + sy) * SXP;
        #pragma unroll
        for (int sx = lane; sx < SX; sx += 32) {
            const int gx = x_t - R + sx;
            float v = 0.0f;
            if (rowvalid && (unsigned)gx < (unsigned)W) v = __ldg(srow + sx);
            drow[sx] = v;
        }
    }
    __syncthreads();

    // ---- gather ----
    const int ty = threadIdx.y;             // 0..15
    const int tx = threadIdx.x;             // 0..31
    const int h  = y_t + ty;
    const int w  = x_t + tx;

    const float* fb = flow + (long long)b * 3 * N;
    float* ob = out + (long long)b * C * N;
    const float* sm1 = sm + CH;

    #pragma unroll
    for (int z = 0; z < TZ; ++z) {
        const int d = z_t + z;
        const long long s = ((long long)d * H + h) * W + w;

        const float fzv = fb[s];
        const float fyv = fb[s + N];
        const float fxv = fb[s + 2 * N];

        // local sample coords within smem tile
        const float lz = (float)(z + R) + fzv;
        const float ly = (float)(ty + R) + fyv;
        const float lx = (float)(tx + R) + fxv;

        const float z0f = floorf(lz), y0f = floorf(ly), x0f = floorf(lx);
        const float fz = lz - z0f, fy = ly - y0f, fx = lx - x0f;
        const int z0 = (int)z0f, y0 = (int)y0f, x0 = (int)x0f;
        const float gz = 1.0f - fz, gy = 1.0f - fy, gx = 1.0f - fx;

        const float w00 = gz * gy, w01 = gz * fy, w10 = fz * gy, w11 = fz * fy;
        const float w000 = w00 * gx, w001 = w00 * fx;
        const float w010 = w01 * gx, w011 = w01 * fx;
        const float w100 = w10 * gx, w101 = w10 * fx;
        const float w110 = w11 * gx, w111 = w11 * fx;

        float a0, a1;

        if (z0 >= 0 && z0 <= SZ - 2 && y0 >= 0 && y0 <= SY - 2 &&
            x0 >= 0 && x0 <= SX - 2) {
            // smem gather (covers both interior and zero-padded halo)
            const int base = (z0 * SY + y0) * SXP + x0;
            const float* p0 = sm  + base;
            const float* p1 = sm1 + base;
            const int rY = SXP, rZ = SY * SXP;
            a0 = w000 * p0[0]       + w001 * p0[1]
               + w010 * p0[rY]      + w011 * p0[rY + 1]
               + w100 * p0[rZ]      + w101 * p0[rZ + 1]
               + w110 * p0[rZ + rY] + w111 * p0[rZ + rY + 1];
            a1 = w000 * p1[0]       + w001 * p1[1]
               + w010 * p1[rY]      + w011 * p1[rY + 1]
               + w100 * p1[rZ]      + w101 * p1[rZ + 1]
               + w110 * p1[rZ + rY] + w111 * p1[rZ + rY + 1];
        } else {
            // rare fallback: sample escapes the tile (|flow| > R) — global path
            a0 = 0.0f; a1 = 0.0f;
            const int gz0 = z0 + z_t - R;   // global corner coords
            const int gy0 = y0 + y_t - R;
            const int gx0 = x0 + x_t - R;
            const float* s0 = src + src_b;
            const float* s1 = s0 + N;
            #pragma unroll
            for (int dz = 0; dz < 2; ++dz) {
                const int zi = gz0 + dz;
                if ((unsigned)zi >= (unsigned)D) continue;
                const float wz = dz ? fz : gz;
                #pragma unroll
                for (int dy = 0; dy < 2; ++dy) {
                    const int yi = gy0 + dy;
                    if ((unsigned)yi >= (unsigned)H) continue;
                    const float wzy = wz * (dy ? fy : gy);
                    #pragma unroll
                    for (int dx = 0; dx < 2; ++dx) {
                        const int xi = gx0 + dx;
                        if ((unsigned)xi >= (unsigned)W) continue;
                        const float wgt = wzy * (dx ? fx : gx);
                        const long long lin = ((long long)zi * H + yi) * W + xi;
                        a0 += wgt * s0[lin];
                        a1 += wgt * s1[lin];
                    }
                }
            }
        }

        ob[s]     = a0;
        ob[s + N] = a1;
    }
}

extern "C" void kernel_launch(void* const* d_in, const int* in_sizes, int n_in,
                              void* d_out, int out_size)
{
    const float* src  = (const float*)d_in[0];
    const float* flow = (const float*)d_in[1];
    float* out = (float*)d_out;

    static bool attr_done = false;
    if (!attr_done) {
        cudaFuncSetAttribute(st_smem_kernel,
                             cudaFuncAttributeMaxDynamicSharedMemorySize,
                             SMEM_BYTES);
        attr_done = true;
    }

    dim3 block(TX, TY, 1);                      // 512 threads
    dim3 grid(W / TX, H / TY, NZT * B);         // 5, 12, 40
    st_smem_kernel<<<grid, block, SMEM_BYTES>>>(src, flow, out);
}

// round 3
// speedup vs baseline: 1.1537x; 1.1537x over previous
#include <cuda_runtime.h>

// VoxelMorph SpatialTransformer, trilinear, zero padding, direct gather.
// src:  [B=2, C=2, 160, 192, 160] f32
// flow: [B=2, 3,   160, 192, 160] f32  (dz, dy, dx)
// out:  [B=2, C=2, 160, 192, 160] f32

namespace {
constexpr int D = 160, H = 192, W = 160, C = 2, B = 2;
constexpr long long N  = (long long)D * H * W;
constexpr long long HW = (long long)H * W;
}

// Load src[row + x0] and src[row + x0 + 1] with one aligned float4 (plus a
// predicated scalar for the 25% of lanes where x0 % 4 == 3).
// Preconditions: 0 <= x0 <= W-2, row 16B-aligned.
__device__ __forceinline__ float2 ld_pair(const float* __restrict__ row, int x0)
{
    const int e = x0 & ~3;
    const int o = x0 & 3;
    const float4 q = __ldg((const float4*)(row + e));
    const float va = (o == 0) ? q.x : (o == 1) ? q.y : (o == 2) ? q.z : q.w;
    float vb;
    if (o == 3) vb = __ldg(row + e + 4);
    else        vb = (o == 0) ? q.y : (o == 1) ? q.z : q.w;
    return make_float2(va, vb);
}

__global__ __launch_bounds__(256)
void st_warp_kernel(const float* __restrict__ src,
                    const float* __restrict__ flow,
                    float* __restrict__ out)
{
    long long s = (long long)blockIdx.x * blockDim.x + threadIdx.x;
    if (s >= N) return;
    const int b = blockIdx.y;

    const int w = (int)(s % W);
    const int t = (int)(s / W);
    const int h = t % H;
    const int d = t / H;

    const float* fb = flow + (long long)b * 3 * N;
    const float z = (float)d + fb[s];
    const float y = (float)h + fb[s + N];
    const float x = (float)w + fb[s + 2 * N];

    const float z0f = floorf(z), y0f = floorf(y), x0f = floorf(x);
    const float fz = z - z0f, fy = y - y0f, fx = x - x0f;
    const int z0 = (int)z0f, y0 = (int)y0f, x0 = (int)x0f;
    const float gz = 1.0f - fz, gy = 1.0f - fy, gx = 1.0f - fx;

    const float* s0 = src + (long long)b * C * N;   // channel 0
    const float* s1 = s0 + N;                       // channel 1

    float a0 = 0.0f, a1 = 0.0f;

    if (z0 >= 0 && z0 < D - 1 && y0 >= 0 && y0 < H - 1 && x0 >= 0 && x0 < W - 1) {
        // interior: all 8 corners in-bounds
        const long long rbase = ((long long)z0 * H + y0) * W;   // row (z0,y0)
        const float w00 = gz * gy, w01 = gz * fy, w10 = fz * gy, w11 = fz * fy;

        // channel 0: 4 corner rows
        {
            const float2 p00 = ld_pair(s0 + rbase,          x0);
            const float2 p01 = ld_pair(s0 + rbase + W,      x0);
            const float2 p10 = ld_pair(s0 + rbase + HW,     x0);
            const float2 p11 = ld_pair(s0 + rbase + HW + W, x0);
            a0 = w00 * (gx * p00.x + fx * p00.y)
               + w01 * (gx * p01.x + fx * p01.y)
               + w10 * (gx * p10.x + fx * p10.y)
               + w11 * (gx * p11.x + fx * p11.y);
        }
        // channel 1
        {
            const float2 p00 = ld_pair(s1 + rbase,          x0);
            const float2 p01 = ld_pair(s1 + rbase + W,      x0);
            const float2 p10 = ld_pair(s1 + rbase + HW,     x0);
            const float2 p11 = ld_pair(s1 + rbase + HW + W, x0);
            a1 = w00 * (gx * p00.x + fx * p00.y)
               + w01 * (gx * p01.x + fx * p01.y)
               + w10 * (gx * p10.x + fx * p10.y)
               + w11 * (gx * p11.x + fx * p11.y);
        }
    } else {
        // boundary: per-corner validity (zero padding)
        #pragma unroll
        for (int dz = 0; dz < 2; ++dz) {
            const int zi = z0 + dz;
            if ((unsigned)zi >= (unsigned)D) continue;
            const float wz = dz ? fz : gz;
            #pragma unroll
            for (int dy = 0; dy < 2; ++dy) {
                const int yi = y0 + dy;
                if ((unsigned)yi >= (unsigned)H) continue;
                const float wzy = wz * (dy ? fy : gy);
                #pragma unroll
                for (int dx = 0; dx < 2; ++dx) {
                    const int xi = x0 + dx;
                    if ((unsigned)xi >= (unsigned)W) continue;
                    const float wgt = wzy * (dx ? fx : gx);
                    const long long lin = ((long long)zi * H + yi) * W + xi;
                    a0 += wgt * s0[lin];
                    a1 += wgt * s1[lin];
                }
            }
        }
    }

    float* ob = out + (long long)b * C * N;
    ob[s]     = a0;
    ob[s + N] = a1;
}

extern "C" void kernel_launch(void* const* d_in, const int* in_sizes, int n_in,
                              void* d_out, int out_size)
{
    const float* src  = (const float*)d_in[0];
    const float* flow = (const float*)d_in[1];
    float* out = (float*)d_out;

    dim3 block(256);
    dim3 grid((unsigned)((N + 255) / 256), B, 1);
    st_warp_kernel<<<grid, block>>>(src, flow, out);
}

// round 4
// speedup vs baseline: 1.5828x; 1.3719x over previous
#include <cuda_runtime.h>

// VoxelMorph SpatialTransformer, trilinear, zero padding, direct gather.
// Warp lanes mapped to an 8x2x2 (x,y,z) patch to shrink the per-gather
// cache-line footprint (L1tex wavefronts are the bottleneck).
// src:  [B=2, C=2, 160, 192, 160] f32
// flow: [B=2, 3,   160, 192, 160] f32  (dz, dy, dx)
// out:  [B=2, C=2, 160, 192, 160] f32

namespace {
constexpr int D = 160, H = 192, W = 160, C = 2, B = 2;
constexpr int N  = D * H * W;           // 4,915,200  (fits int32; B*C*N < 2^31)
constexpr int HW = H * W;
constexpr int ZT = D / 2;               // 80 z-tiles of 2
}

__global__ __launch_bounds__(256)
void st_patch_kernel(const float* __restrict__ src,
                     const float* __restrict__ flow,
                     float* __restrict__ out)
{
    // block tile: 32(x) x 4(y) x 2(z)
    const int bx  = blockIdx.x * 32;
    const int by  = blockIdx.y * 4;
    const int bzz = blockIdx.z;              // 0 .. B*ZT-1
    const int b   = bzz / ZT;
    const int bz  = (bzz - b * ZT) * 2;

    const int tid  = threadIdx.x;
    const int lane = tid & 31;
    const int warp = tid >> 5;               // 0..7
    // lane -> 8x2x2 patch
    const int lx = lane & 7;
    const int ly = (lane >> 3) & 1;
    const int lz = lane >> 4;
    // warp -> 4x2x1 arrangement of patches
    const int wx = warp & 3;
    const int wy = warp >> 2;

    const int w = bx + wx * 8 + lx;
    const int h = by + wy * 2 + ly;
    const int d = bz + lz;

    const int s = (d * H + h) * W + w;

    const float* fb = flow + b * 3 * N;
    const float z = (float)d + fb[s];
    const float y = (float)h + fb[s + N];
    const float x = (float)w + fb[s + 2 * N];

    const float z0f = floorf(z), y0f = floorf(y), x0f = floorf(x);
    const float fz = z - z0f, fy = y - y0f, fx = x - x0f;
    const int z0 = (int)z0f, y0 = (int)y0f, x0 = (int)x0f;
    const float gz = 1.0f - fz, gy = 1.0f - fy, gx = 1.0f - fx;

    const float* s0 = src + b * C * N;       // channel 0
    const float* s1 = s0 + N;                // channel 1

    float a0 = 0.0f, a1 = 0.0f;

    if (z0 >= 0 && z0 < D - 1 && y0 >= 0 && y0 < H - 1 && x0 >= 0 && x0 < W - 1) {
        // interior fast path: all 8 corners in-bounds, scalar LDGs
        const int base = (z0 * H + y0) * W + x0;
        const float w00 = gz * gy, w01 = gz * fy, w10 = fz * gy, w11 = fz * fy;
        const float w000 = w00 * gx, w001 = w00 * fx;
        const float w010 = w01 * gx, w011 = w01 * fx;
        const float w100 = w10 * gx, w101 = w10 * fx;
        const float w110 = w11 * gx, w111 = w11 * fx;

        const float* p0 = s0 + base;
        const float* p1 = s1 + base;
        a0 = w000 * __ldg(p0)          + w001 * __ldg(p0 + 1)
           + w010 * __ldg(p0 + W)      + w011 * __ldg(p0 + W + 1)
           + w100 * __ldg(p0 + HW)     + w101 * __ldg(p0 + HW + 1)
           + w110 * __ldg(p0 + HW + W) + w111 * __ldg(p0 + HW + W + 1);
        a1 = w000 * __ldg(p1)          + w001 * __ldg(p1 + 1)
           + w010 * __ldg(p1 + W)      + w011 * __ldg(p1 + W + 1)
           + w100 * __ldg(p1 + HW)     + w101 * __ldg(p1 + HW + 1)
           + w110 * __ldg(p1 + HW + W) + w111 * __ldg(p1 + HW + W + 1);
    } else {
        // boundary path: per-corner validity (zero padding)
        #pragma unroll
        for (int dz = 0; dz < 2; ++dz) {
            const int zi = z0 + dz;
            if ((unsigned)zi >= (unsigned)D) continue;
            const float wz = dz ? fz : gz;
            #pragma unroll
            for (int dy = 0; dy < 2; ++dy) {
                const int yi = y0 + dy;
                if ((unsigned)yi >= (unsigned)H) continue;
                const float wzy = wz * (dy ? fy : gy);
                #pragma unroll
                for (int dx = 0; dx < 2; ++dx) {
                    const int xi = x0 + dx;
                    if ((unsigned)xi >= (unsigned)W) continue;
                    const float wgt = wzy * (dx ? fx : gx);
                    const int lin = (zi * H + yi) * W + xi;
                    a0 += wgt * __ldg(s0 + lin);
                    a1 += wgt * __ldg(s1 + lin);
                }
            }
        }
    }

    float* ob = out + b * C * N;
    ob[s]     = a0;
    ob[s + N] = a1;
}

extern "C" void kernel_launch(void* const* d_in, const int* in_sizes, int n_in,
                              void* d_out, int out_size)
{
    const float* src  = (const float*)d_in[0];
    const float* flow = (const float*)d_in[1];
    float* out = (float*)d_out;

    dim3 block(256);
    dim3 grid(W / 32, H / 4, B * ZT);    // 5, 48, 160
    st_patch_kernel<<<grid, block>>>(src, flow, out);
}